// round 5
// baseline (speedup 1.0000x reference)
#include <cuda_runtime.h>
#include <cuda_bf16.h>
#include <math.h>

#define NB 8
#define SL 4096
#define HD 128
#define CCH 128
#define NCH (SL / CCH)   // 32
#define NT  (NB * NCH)   // 256 tiles

#define TPAD 136                     // padded bf16 row stride in smem tiles
#define TILE_BYTES (128 * TPAD * 2)  // 34816

typedef unsigned int u32;

// ---------------------------------------------------------------------------
// Scratch (no allocations allowed)
// ---------------------------------------------------------------------------
__device__ float g_cos[SL * HD];
__device__ float g_sin[SL * HD];
__device__ float g_h  [NT * HD * HD];           // per-chunk H[d][e] fp32
__device__ __nv_bfloat16 g_q_hi [NT * 16384];   // Qr  [t][d]
__device__ __nv_bfloat16 g_q_lo [NT * 16384];
__device__ __nv_bfloat16 g_kT_hi[NT * 16384];   // Kr^T [d][t]
__device__ __nv_bfloat16 g_kT_lo[NT * 16384];
__device__ __nv_bfloat16 g_v_hi [NT * 16384];   // V   [t][e]
__device__ __nv_bfloat16 g_v_lo [NT * 16384];
__device__ __nv_bfloat16 g_s_hi [NT * 16384];   // S excl prefix [d][e]
__device__ __nv_bfloat16 g_s_lo [NT * 16384];

// ---------------------------------------------------------------------------
// Warp MMA + async-copy primitives (baseline PTX, valid on plain sm_100)
// ---------------------------------------------------------------------------
__device__ __forceinline__ u32 smem_u32(const void* p) {
    u32 a;
    asm("{ .reg .u64 t; cvta.to.shared.u64 t, %1; cvt.u32.u64 %0, t; }"
        : "=r"(a) : "l"(p));
    return a;
}
__device__ __forceinline__ void ldsm4(u32& r0, u32& r1, u32& r2, u32& r3, u32 a) {
    asm volatile("ldmatrix.sync.aligned.m8n8.x4.shared.b16 {%0,%1,%2,%3}, [%4];"
                 : "=r"(r0), "=r"(r1), "=r"(r2), "=r"(r3) : "r"(a));
}
__device__ __forceinline__ void ldsm4t(u32& r0, u32& r1, u32& r2, u32& r3, u32 a) {
    asm volatile("ldmatrix.sync.aligned.m8n8.x4.trans.shared.b16 {%0,%1,%2,%3}, [%4];"
                 : "=r"(r0), "=r"(r1), "=r"(r2), "=r"(r3) : "r"(a));
}
__device__ __forceinline__ void mma_bf16(float* c, u32 a0, u32 a1, u32 a2, u32 a3,
                                         u32 b0, u32 b1) {
    asm volatile(
        "mma.sync.aligned.m16n8k16.row.col.f32.bf16.bf16.f32 "
        "{%0,%1,%2,%3},{%4,%5,%6,%7},{%8,%9},{%0,%1,%2,%3};"
        : "+f"(c[0]), "+f"(c[1]), "+f"(c[2]), "+f"(c[3])
        : "r"(a0), "r"(a1), "r"(a2), "r"(a3), "r"(b0), "r"(b1));
}
__device__ __forceinline__ void cp16(u32 dst, const void* src) {
    asm volatile("cp.async.cg.shared.global [%0], [%1], 16;"
                 :: "r"(dst), "l"(src) : "memory");
}
__device__ __forceinline__ void cp_commit() {
    asm volatile("cp.async.commit_group;" ::: "memory");
}
__device__ __forceinline__ void cp_wait0() {
    asm volatile("cp.async.wait_group 0;" ::: "memory");
}
__device__ __forceinline__ u32 packbf(__nv_bfloat16 lo, __nv_bfloat16 hi) {
    return (u32)__bfloat16_as_ushort(hi) << 16 | (u32)__bfloat16_as_ushort(lo);
}
__device__ __forceinline__ void split_store(__nv_bfloat16* hi, __nv_bfloat16* lo,
                                            int off, float v) {
    __nv_bfloat16 h = __float2bfloat16(v);
    hi[off] = h;
    lo[off] = __float2bfloat16(v - __bfloat162float(h));
}

// gmem [128][128] bf16 tile -> padded smem tile, via cp.async (16B granules)
__device__ __forceinline__ void copy_tile_async(u32 dst, const __nv_bfloat16* src,
                                                int tid) {
    #pragma unroll
    for (int i = 0; i < 8; ++i) {
        int j = tid + i * 256;
        int row = j >> 4, col = j & 15;
        cp16(dst + row * (TPAD * 2) + col * 16, (const char*)src + j * 16);
    }
}
// padded smem tile -> compact gmem tile (coalesced uint4)
__device__ __forceinline__ void store_tile(__nv_bfloat16* dst, const char* src,
                                           int tid) {
    #pragma unroll
    for (int i = 0; i < 8; ++i) {
        int j = tid + i * 256;
        int row = j >> 4, col = j & 15;
        ((uint4*)dst)[j] = *(const uint4*)(src + row * (TPAD * 2) + col * 16);
    }
}

// ---------------------------------------------------------------------------
// 3-term split GEMM, warp tile 16x128, K=128.
// ---------------------------------------------------------------------------
__device__ __forceinline__ void gemm3(u32 ah, u32 al, u32 bh, u32 bl,
                                      float acc[16][4], int m0, int lane) {
    int l15 = lane & 15, lhi = (lane >> 4) << 3;
    #pragma unroll 1
    for (int kk = 0; kk < 8; ++kk) {
        u32 aoff = (u32)(((m0 + l15) * TPAD + kk * 16 + lhi) * 2);
        u32 A0, A1, A2, A3, L0, L1, L2, L3;
        ldsm4(A0, A1, A2, A3, ah + aoff);
        ldsm4(L0, L1, L2, L3, al + aoff);
        #pragma unroll
        for (int nt = 0; nt < 8; ++nt) {
            u32 boff = (u32)(((kk * 16 + l15) * TPAD + nt * 16 + lhi) * 2);
            u32 B0, B1, B2, B3, C0, C1, C2, C3;
            ldsm4t(B0, B1, B2, B3, bh + boff);
            ldsm4t(C0, C1, C2, C3, bl + boff);
            mma_bf16(acc[2 * nt],     A0, A1, A2, A3, B0, B1);
            mma_bf16(acc[2 * nt + 1], A0, A1, A2, A3, B2, B3);
            mma_bf16(acc[2 * nt],     A0, A1, A2, A3, C0, C1);
            mma_bf16(acc[2 * nt + 1], A0, A1, A2, A3, C2, C3);
            mma_bf16(acc[2 * nt],     L0, L1, L2, L3, B0, B1);
            mma_bf16(acc[2 * nt + 1], L0, L1, L2, L3, B2, B3);
        }
    }
}

// Same, but A comes from in-register E fragments, K=128.
__device__ __forceinline__ void gemm_e(const u32 eh[16][2], const u32 el[16][2],
                                       u32 bh, u32 bl, float acc[16][4], int lane) {
    int l15 = lane & 15, lhi = (lane >> 4) << 3;
    #pragma unroll
    for (int kk = 0; kk < 8; ++kk) {
        u32 A0 = eh[2 * kk][0], A1 = eh[2 * kk][1];
        u32 A2 = eh[2 * kk + 1][0], A3 = eh[2 * kk + 1][1];
        u32 L0 = el[2 * kk][0], L1 = el[2 * kk][1];
        u32 L2 = el[2 * kk + 1][0], L3 = el[2 * kk + 1][1];
        #pragma unroll
        for (int nt = 0; nt < 8; ++nt) {
            u32 boff = (u32)(((kk * 16 + l15) * TPAD + nt * 16 + lhi) * 2);
            u32 B0, B1, B2, B3, C0, C1, C2, C3;
            ldsm4t(B0, B1, B2, B3, bh + boff);
            ldsm4t(C0, C1, C2, C3, bl + boff);
            mma_bf16(acc[2 * nt],     A0, A1, A2, A3, B0, B1);
            mma_bf16(acc[2 * nt + 1], A0, A1, A2, A3, B2, B3);
            mma_bf16(acc[2 * nt],     A0, A1, A2, A3, C0, C1);
            mma_bf16(acc[2 * nt + 1], A0, A1, A2, A3, C2, C3);
            mma_bf16(acc[2 * nt],     L0, L1, L2, L3, B0, B1);
            mma_bf16(acc[2 * nt + 1], L0, L1, L2, L3, B2, B3);
        }
    }
}

// ---------------------------------------------------------------------------
// Kernel 0: RoPE cos/sin table (double internally)
// ---------------------------------------------------------------------------
__global__ void k_tab() {
    int s = blockIdx.x;
    int j = threadIdx.x;
    int j2 = j & 63;
    double inv = exp(-(double)j2 * (log(10000.0) / 64.0));
    double a = (double)s * inv;
    double sv, cv;
    sincos(a, &sv, &cv);
    g_cos[s * HD + j] = (float)cv;
    g_sin[s * HD + j] = (float)sv;
}

// ---------------------------------------------------------------------------
// Kernel 1 (fused rope + H): per (b, chunk):
//   rope Q -> g_q;  rope K -> smem kT tiles -> g_kT;  V -> smem tiles -> g_v;
//   H[d][e] = sum_t KrT[d][t]*V[t][e] via HMMA -> g_h.
// smem: sKTh@0, sKTl@T, sVh@2T, sVl@3T, fbuf(float [128][129])@4T => 205312 B
// ---------------------------------------------------------------------------
__global__ void __launch_bounds__(256) k_prep(const float* __restrict__ Q,
                                              const float* __restrict__ K,
                                              const float* __restrict__ V) {
    extern __shared__ char sm[];
    u32 sb = smem_u32(sm);
    __nv_bfloat16* sKTh = (__nv_bfloat16*)sm;
    __nv_bfloat16* sKTl = (__nv_bfloat16*)(sm + TILE_BYTES);
    __nv_bfloat16* sVh  = (__nv_bfloat16*)(sm + 2 * TILE_BYTES);
    __nv_bfloat16* sVl  = (__nv_bfloat16*)(sm + 3 * TILE_BYTES);
    float* fbuf = (float*)(sm + 4 * TILE_BYTES);   // [128][129]

    int tile = blockIdx.x;
    int b = tile >> 5, ch = tile & 31;
    int tid = threadIdx.x, lane = tid & 31, wid = tid >> 5;
    int base  = (b * SL + ch * CCH) * HD;
    int tbase = tile * 16384;

    // pass 1: rope Q -> gmem; V -> smem tiles; roped K -> fbuf
    #pragma unroll 4
    for (int i = 0; i < 64; ++i) {
        int idx = tid + i * 256;
        int t = idx >> 7, d = idx & 127;
        int s = ch * CCH + t;
        float cs = g_cos[s * HD + d], sn = g_sin[s * HD + d];
        float x  = Q[base + idx];
        float xo = Q[base + (idx ^ 64)];
        float rot = (d < 64) ? -xo : xo;
        split_store(g_q_hi, g_q_lo, tbase + idx, x * cs + rot * sn);
        float vv = V[base + idx];
        __nv_bfloat16 vh = __float2bfloat16(vv);
        sVh[t * TPAD + d] = vh;
        sVl[t * TPAD + d] = __float2bfloat16(vv - __bfloat162float(vh));
        float kx  = K[base + idx];
        float kxo = K[base + (idx ^ 64)];
        float krot = (d < 64) ? -kxo : kxo;
        fbuf[t * 129 + d] = kx * cs + krot * sn;
    }
    __syncthreads();

    // pass 2: transpose roped K into smem tiles
    #pragma unroll 4
    for (int i = 0; i < 64; ++i) {
        int idx = tid + i * 256;
        int d = idx >> 7, t = idx & 127;
        float v = fbuf[t * 129 + d];
        __nv_bfloat16 h = __float2bfloat16(v);
        sKTh[d * TPAD + t] = h;
        sKTl[d * TPAD + t] = __float2bfloat16(v - __bfloat162float(h));
    }
    __syncthreads();

    // pass 3: smem tiles -> gmem (coalesced) — reads only, no sync needed after
    store_tile(g_kT_hi + tbase, sm,                  tid);
    store_tile(g_kT_lo + tbase, sm + TILE_BYTES,     tid);
    store_tile(g_v_hi  + tbase, sm + 2 * TILE_BYTES, tid);
    store_tile(g_v_lo  + tbase, sm + 3 * TILE_BYTES, tid);

    // pass 4: H = KrT @ V (3-term HMMA)
    float acc[16][4] = {};
    int m0 = wid * 16;
    gemm3(sb, sb + TILE_BYTES, sb + 2 * TILE_BYTES, sb + 3 * TILE_BYTES,
          acc, m0, lane);

    int r = m0 + (lane >> 2), cb = (lane & 3) * 2;
    float* dst = g_h + tbase;
    #pragma unroll
    for (int j = 0; j < 16; ++j) {
        int c = 8 * j + cb;
        *(float2*)(dst + r * 128 + c)       = make_float2(acc[j][0], acc[j][1]);
        *(float2*)(dst + (r + 8) * 128 + c) = make_float2(acc[j][2], acc[j][3]);
    }
}

// ---------------------------------------------------------------------------
// Kernel 2: exclusive prefix scan of H over chunks -> split-bf16 S tiles.
// ---------------------------------------------------------------------------
__global__ void __launch_bounds__(128) k_scan() {
    int b = blockIdx.x, d = blockIdx.y, e = threadIdx.x;
    float vals[NCH];
    #pragma unroll
    for (int i = 0; i < NCH; ++i)
        vals[i] = g_h[(b * NCH + i) * 16384 + d * 128 + e];
    int o = d * 128 + e;
    float run = 0.f;
    #pragma unroll
    for (int i = 0; i < NCH; ++i) {
        int tb = (b * NCH + i) * 16384;
        split_store(g_s_hi, g_s_lo, tb + o, run);
        run += vals[i];
    }
}

// ---------------------------------------------------------------------------
// Kernel 3: out = tril(Qr Kr^T) V + Qr S  per (b, chunk). cp.async pipelined.
// smem slots (6 x TILE_BYTES = 208896): Q(0,1), KT(2,3)->V, S(4,5).
// ---------------------------------------------------------------------------
__global__ void __launch_bounds__(256) k_out(float* __restrict__ out) {
    extern __shared__ char sm[];
    u32 sb = smem_u32(sm);
    int tile = blockIdx.x;
    int tid = threadIdx.x, lane = tid & 31, wid = tid >> 5;
    int qb = tile * 16384;
    int m0 = wid * 16;

    // async load Q, KT, S
    copy_tile_async(sb,                  g_q_hi  + qb, tid);
    copy_tile_async(sb + TILE_BYTES,     g_q_lo  + qb, tid);
    copy_tile_async(sb + 2 * TILE_BYTES, g_kT_hi + qb, tid);
    copy_tile_async(sb + 3 * TILE_BYTES, g_kT_lo + qb, tid);
    copy_tile_async(sb + 4 * TILE_BYTES, g_s_hi  + qb, tid);
    copy_tile_async(sb + 5 * TILE_BYTES, g_s_lo  + qb, tid);
    cp_commit();
    cp_wait0();
    __syncthreads();

    // phase 1: E = Qr @ Kr^T
    float eacc[16][4] = {};
    gemm3(sb, sb + TILE_BYTES, sb + 2 * TILE_BYTES, sb + 3 * TILE_BYTES,
          eacc, m0, lane);

    // mask + split to bf16 A-fragments in registers
    u32 eh[16][2], el[16][2];
    {
        int r = m0 + (lane >> 2), cb = (lane & 3) * 2;
        #pragma unroll
        for (int j = 0; j < 16; ++j) {
            int c = 8 * j + cb;
            float v0 = (c     <= r)     ? eacc[j][0] : 0.f;
            float v1 = (c + 1 <= r)     ? eacc[j][1] : 0.f;
            float v2 = (c     <= r + 8) ? eacc[j][2] : 0.f;
            float v3 = (c + 1 <= r + 8) ? eacc[j][3] : 0.f;
            __nv_bfloat16 h0 = __float2bfloat16(v0), h1 = __float2bfloat16(v1);
            __nv_bfloat16 h2 = __float2bfloat16(v2), h3 = __float2bfloat16(v3);
            eh[j][0] = packbf(h0, h1);
            eh[j][1] = packbf(h2, h3);
            el[j][0] = packbf(__float2bfloat16(v0 - __bfloat162float(h0)),
                              __float2bfloat16(v1 - __bfloat162float(h1)));
            el[j][1] = packbf(__float2bfloat16(v2 - __bfloat162float(h2)),
                              __float2bfloat16(v3 - __bfloat162float(h3)));
        }
    }
    __syncthreads();   // all warps done reading KT slots

    // prefetch V into KT slots; overlaps with phase 2 compute
    copy_tile_async(sb + 2 * TILE_BYTES, g_v_hi + qb, tid);
    copy_tile_async(sb + 3 * TILE_BYTES, g_v_lo + qb, tid);
    cp_commit();

    // phase 2: O = Qr @ S
    float oacc[16][4] = {};
    gemm3(sb, sb + TILE_BYTES, sb + 4 * TILE_BYTES, sb + 5 * TILE_BYTES,
          oacc, m0, lane);

    cp_wait0();
    __syncthreads();

    // phase 3: O += E @ V  (A from registers)
    gemm_e(eh, el, sb + 2 * TILE_BYTES, sb + 3 * TILE_BYTES, oacc, lane);

    // epilogue
    int r = m0 + (lane >> 2), cb = (lane & 3) * 2;
    float* dst = out + qb;
    #pragma unroll
    for (int j = 0; j < 16; ++j) {
        int c = 8 * j + cb;
        *(float2*)(dst + r * 128 + c)       = make_float2(oacc[j][0], oacc[j][1]);
        *(float2*)(dst + (r + 8) * 128 + c) = make_float2(oacc[j][2], oacc[j][3]);
    }
}

// ---------------------------------------------------------------------------
extern "C" void kernel_launch(void* const* d_in, const int* in_sizes, int n_in,
                              void* d_out, int out_size) {
    (void)in_sizes; (void)n_in; (void)out_size;
    const float* Q = (const float*)d_in[0];
    const float* K = (const float*)d_in[1];
    const float* V = (const float*)d_in[2];
    float* out = (float*)d_out;

    const int prep_smem = 4 * TILE_BYTES + 128 * 129 * 4;   // 205312
    const int out_smem  = 6 * TILE_BYTES;                   // 208896
    cudaFuncSetAttribute(k_prep, cudaFuncAttributeMaxDynamicSharedMemorySize, prep_smem);
    cudaFuncSetAttribute(k_out,  cudaFuncAttributeMaxDynamicSharedMemorySize, out_smem);

    k_tab <<<SL, HD>>>();
    k_prep<<<NT, 256, prep_smem>>>(Q, K, V);
    k_scan<<<dim3(NB, HD), 128>>>();
    k_out <<<NT, 256, out_smem>>>(out);
}

// round 6
// speedup vs baseline: 1.2126x; 1.2126x over previous
#include <cuda_runtime.h>
#include <cuda_bf16.h>
#include <math.h>

#define NB 8
#define SL 4096
#define HD 128
#define CCH 128
#define NCH (SL / CCH)   // 32
#define NT  (NB * NCH)   // 256 tiles

#define TPAD 136                     // padded bf16 row stride in smem tiles
#define TILE_BYTES (128 * TPAD * 2)  // 34816

typedef unsigned int u32;

// ---------------------------------------------------------------------------
// Scratch (no allocations allowed)
// ---------------------------------------------------------------------------
__device__ float g_cos[SL * HD];
__device__ float g_sin[SL * HD];
__device__ float g_h  [NT * HD * HD];           // per-chunk H[d][e] fp32
__device__ __nv_bfloat16 g_q_hi [NT * 16384];   // Qr  [t][d]
__device__ __nv_bfloat16 g_q_lo [NT * 16384];
__device__ __nv_bfloat16 g_kT_hi[NT * 16384];   // Kr^T [d][t]
__device__ __nv_bfloat16 g_kT_lo[NT * 16384];
__device__ __nv_bfloat16 g_v_hi [NT * 16384];   // V   [t][e]
__device__ __nv_bfloat16 g_v_lo [NT * 16384];
__device__ __nv_bfloat16 g_s_hi [NT * 16384];   // S excl prefix [d][e]
__device__ __nv_bfloat16 g_s_lo [NT * 16384];

// ---------------------------------------------------------------------------
// Warp MMA + async-copy primitives (baseline PTX, valid on plain sm_100)
// ---------------------------------------------------------------------------
__device__ __forceinline__ u32 smem_u32(const void* p) {
    u32 a;
    asm("{ .reg .u64 t; cvta.to.shared.u64 t, %1; cvt.u32.u64 %0, t; }"
        : "=r"(a) : "l"(p));
    return a;
}
__device__ __forceinline__ void ldsm4(u32& r0, u32& r1, u32& r2, u32& r3, u32 a) {
    asm volatile("ldmatrix.sync.aligned.m8n8.x4.shared.b16 {%0,%1,%2,%3}, [%4];"
                 : "=r"(r0), "=r"(r1), "=r"(r2), "=r"(r3) : "r"(a));
}
__device__ __forceinline__ void ldsm4t(u32& r0, u32& r1, u32& r2, u32& r3, u32 a) {
    asm volatile("ldmatrix.sync.aligned.m8n8.x4.trans.shared.b16 {%0,%1,%2,%3}, [%4];"
                 : "=r"(r0), "=r"(r1), "=r"(r2), "=r"(r3) : "r"(a));
}
__device__ __forceinline__ void mma_bf16(float* c, u32 a0, u32 a1, u32 a2, u32 a3,
                                         u32 b0, u32 b1) {
    asm volatile(
        "mma.sync.aligned.m16n8k16.row.col.f32.bf16.bf16.f32 "
        "{%0,%1,%2,%3},{%4,%5,%6,%7},{%8,%9},{%0,%1,%2,%3};"
        : "+f"(c[0]), "+f"(c[1]), "+f"(c[2]), "+f"(c[3])
        : "r"(a0), "r"(a1), "r"(a2), "r"(a3), "r"(b0), "r"(b1));
}
__device__ __forceinline__ void cp16(u32 dst, const void* src) {
    asm volatile("cp.async.cg.shared.global [%0], [%1], 16;"
                 :: "r"(dst), "l"(src) : "memory");
}
__device__ __forceinline__ void cp_commit() {
    asm volatile("cp.async.commit_group;" ::: "memory");
}
__device__ __forceinline__ void cp_wait0() {
    asm volatile("cp.async.wait_group 0;" ::: "memory");
}
__device__ __forceinline__ u32 packbf(__nv_bfloat16 lo, __nv_bfloat16 hi) {
    return (u32)__bfloat16_as_ushort(hi) << 16 | (u32)__bfloat16_as_ushort(lo);
}
__device__ __forceinline__ void split_store(__nv_bfloat16* hi, __nv_bfloat16* lo,
                                            int off, float v) {
    __nv_bfloat16 h = __float2bfloat16(v);
    hi[off] = h;
    lo[off] = __float2bfloat16(v - __bfloat162float(h));
}

// gmem [128][128] bf16 tile -> padded smem tile, via cp.async (16B granules)
__device__ __forceinline__ void copy_tile_async(u32 dst, const __nv_bfloat16* src,
                                                int tid) {
    #pragma unroll
    for (int i = 0; i < 8; ++i) {
        int j = tid + i * 256;
        int row = j >> 4, col = j & 15;
        cp16(dst + row * (TPAD * 2) + col * 16, (const char*)src + j * 16);
    }
}

// ---------------------------------------------------------------------------
// 3-term split GEMM, warp tile 32x64, K=128.
// Warp grid 4x2: m0 = (wid>>1)*32, n0 = (wid&1)*64.
// acc[16][4]: frag index = rg*8 + nt*2 + h  (rg: 16-row group, nt: 16-col
// group, h: n8 half).
// ---------------------------------------------------------------------------
__device__ __forceinline__ void gemm3(u32 ah, u32 al, u32 bh, u32 bl,
                                      float acc[16][4], int m0, int n0, int lane) {
    int l15 = lane & 15, lhi = (lane >> 4) << 3;
    #pragma unroll 1
    for (int kk = 0; kk < 8; ++kk) {
        u32 ar0 = (u32)(((m0 + l15) * TPAD + kk * 16 + lhi) * 2);
        u32 ar1 = ar0 + 16 * TPAD * 2;
        u32 H0[4], H1[4], L0[4], L1[4];
        ldsm4(H0[0], H0[1], H0[2], H0[3], ah + ar0);
        ldsm4(H1[0], H1[1], H1[2], H1[3], ah + ar1);
        ldsm4(L0[0], L0[1], L0[2], L0[3], al + ar0);
        ldsm4(L1[0], L1[1], L1[2], L1[3], al + ar1);
        #pragma unroll
        for (int nt = 0; nt < 4; ++nt) {
            u32 boff = (u32)(((kk * 16 + l15) * TPAD + n0 + nt * 16 + lhi) * 2);
            u32 B0, B1, B2, B3, C0, C1, C2, C3;
            ldsm4t(B0, B1, B2, B3, bh + boff);
            ldsm4t(C0, C1, C2, C3, bl + boff);
            float* a00 = acc[nt * 2];
            float* a01 = acc[nt * 2 + 1];
            float* a10 = acc[8 + nt * 2];
            float* a11 = acc[8 + nt * 2 + 1];
            mma_bf16(a00, H0[0], H0[1], H0[2], H0[3], B0, B1);
            mma_bf16(a01, H0[0], H0[1], H0[2], H0[3], B2, B3);
            mma_bf16(a10, H1[0], H1[1], H1[2], H1[3], B0, B1);
            mma_bf16(a11, H1[0], H1[1], H1[2], H1[3], B2, B3);
            mma_bf16(a00, H0[0], H0[1], H0[2], H0[3], C0, C1);
            mma_bf16(a01, H0[0], H0[1], H0[2], H0[3], C2, C3);
            mma_bf16(a10, H1[0], H1[1], H1[2], H1[3], C0, C1);
            mma_bf16(a11, H1[0], H1[1], H1[2], H1[3], C2, C3);
            mma_bf16(a00, L0[0], L0[1], L0[2], L0[3], B0, B1);
            mma_bf16(a01, L0[0], L0[1], L0[2], L0[3], B2, B3);
            mma_bf16(a10, L1[0], L1[1], L1[2], L1[3], B0, B1);
            mma_bf16(a11, L1[0], L1[1], L1[2], L1[3], B2, B3);
        }
    }
}

// acc -> gmem fp32 [128][128] tile (warp 32x64 region)
__device__ __forceinline__ void epilogue(float* dst, float acc[16][4],
                                         int m0, int n0, int lane) {
    int r = m0 + (lane >> 2), cb = n0 + (lane & 3) * 2;
    #pragma unroll
    for (int rg = 0; rg < 2; ++rg)
        #pragma unroll
        for (int nt = 0; nt < 4; ++nt)
            #pragma unroll
            for (int h = 0; h < 2; ++h) {
                float* a = acc[rg * 8 + nt * 2 + h];
                int rr = r + rg * 16, c = cb + nt * 16 + h * 8;
                *(float2*)(dst + rr * 128 + c)       = make_float2(a[0], a[1]);
                *(float2*)(dst + (rr + 8) * 128 + c) = make_float2(a[2], a[3]);
            }
}

// ---------------------------------------------------------------------------
// Kernel 0: RoPE cos/sin table (double internally)
// ---------------------------------------------------------------------------
__global__ void k_tab() {
    int s = blockIdx.x;
    int j = threadIdx.x;
    int j2 = j & 63;
    double inv = exp(-(double)j2 * (log(10000.0) / 64.0));
    double a = (double)s * inv;
    double sv, cv;
    sincos(a, &sv, &cv);
    g_cos[s * HD + j] = (float)cv;
    g_sin[s * HD + j] = (float)sv;
}

// ---------------------------------------------------------------------------
// Kernel 1: RoPE + split-bf16. Q -> g_q [t][d]; K -> g_kT [d][t]; V -> g_v.
// 66 KB smem -> 3 CTAs/SM (latency-bound phase needs the occupancy).
// ---------------------------------------------------------------------------
__global__ void __launch_bounds__(256) k_rope(const float* __restrict__ Q,
                                              const float* __restrict__ K,
                                              const float* __restrict__ V) {
    extern __shared__ float buf[];   // [128][129]
    int b  = blockIdx.x >> 5;
    int ch = blockIdx.x & 31;
    int tid = threadIdx.x;
    int base  = (b * SL + ch * CCH) * HD;
    int tbase = blockIdx.x * 16384;

    #pragma unroll 4
    for (int i = 0; i < 64; ++i) {
        int idx = tid + i * 256;
        int t = idx >> 7, d = idx & 127;
        int s = ch * CCH + t;
        float cs = g_cos[s * HD + d], sn = g_sin[s * HD + d];
        float x  = Q[base + idx];
        float xo = Q[base + (idx ^ 64)];
        float rot = (d < 64) ? -xo : xo;
        split_store(g_q_hi, g_q_lo, tbase + idx, x * cs + rot * sn);
        split_store(g_v_hi, g_v_lo, tbase + idx, V[base + idx]);
        float kx  = K[base + idx];
        float kxo = K[base + (idx ^ 64)];
        float krot = (d < 64) ? -kxo : kxo;
        buf[t * 129 + d] = kx * cs + krot * sn;
    }
    __syncthreads();
    #pragma unroll 4
    for (int i = 0; i < 64; ++i) {
        int idx = tid + i * 256;
        int d = idx >> 7, t = idx & 127;
        split_store(g_kT_hi, g_kT_lo, tbase + idx, buf[t * 129 + d]);
    }
}

// ---------------------------------------------------------------------------
// Kernel 2: per-chunk H[d][e] = sum_t Kr^T[d][t] * V[t][e]  (HMMA, 3-term)
// smem: KTh@0, KTl@T, Vh@2T, Vl@3T  (139264 B)
// ---------------------------------------------------------------------------
__global__ void __launch_bounds__(256) k_h() {
    extern __shared__ char sm[];
    u32 sb = smem_u32(sm);
    int tile = blockIdx.x;
    int tid = threadIdx.x, lane = tid & 31, wid = tid >> 5;
    int m0 = (wid >> 1) * 32, n0 = (wid & 1) * 64;
    int tbase = tile * 16384;

    copy_tile_async(sb,                  g_kT_hi + tbase, tid);
    copy_tile_async(sb + TILE_BYTES,     g_kT_lo + tbase, tid);
    copy_tile_async(sb + 2 * TILE_BYTES, g_v_hi  + tbase, tid);
    copy_tile_async(sb + 3 * TILE_BYTES, g_v_lo  + tbase, tid);
    cp_commit();
    cp_wait0();
    __syncthreads();

    float acc[16][4] = {};
    gemm3(sb, sb + TILE_BYTES, sb + 2 * TILE_BYTES, sb + 3 * TILE_BYTES,
          acc, m0, n0, lane);
    epilogue(g_h + tbase, acc, m0, n0, lane);
}

// ---------------------------------------------------------------------------
// Kernel 3: exclusive prefix scan of H over chunks -> split-bf16 S tiles.
// ---------------------------------------------------------------------------
__global__ void __launch_bounds__(128) k_scan() {
    int b = blockIdx.x, d = blockIdx.y, e = threadIdx.x;
    float vals[NCH];
    #pragma unroll
    for (int i = 0; i < NCH; ++i)
        vals[i] = g_h[(b * NCH + i) * 16384 + d * 128 + e];
    int o = d * 128 + e;
    float run = 0.f;
    #pragma unroll
    for (int i = 0; i < NCH; ++i) {
        int tb = (b * NCH + i) * 16384;
        split_store(g_s_hi, g_s_lo, tb + o, run);
        run += vals[i];
    }
}

// ---------------------------------------------------------------------------
// Kernel 4: out = tril(Qr Kr^T) V + Qr S  per (b, chunk).
// Slots (6 x TILE_BYTES = 208896): s0/s1 = Q, s2/s3 = KT -> E, s4/s5 = S -> V.
// Phase order: O=Q*S, then (V prefetch overlaps) E=Q*KT, E masked -> s2/s3,
// then O += E*V.
// ---------------------------------------------------------------------------
__global__ void __launch_bounds__(256) k_out(float* __restrict__ out) {
    extern __shared__ char sm[];
    u32 sb = smem_u32(sm);
    int tile = blockIdx.x;
    int tid = threadIdx.x, lane = tid & 31, wid = tid >> 5;
    int qb = tile * 16384;
    int m0 = (wid >> 1) * 32, n0 = (wid & 1) * 64;

    u32 s0 = sb, s1 = sb + TILE_BYTES, s2 = sb + 2 * TILE_BYTES,
        s3 = sb + 3 * TILE_BYTES, s4 = sb + 4 * TILE_BYTES, s5 = sb + 5 * TILE_BYTES;

    copy_tile_async(s0, g_q_hi  + qb, tid);
    copy_tile_async(s1, g_q_lo  + qb, tid);
    copy_tile_async(s2, g_kT_hi + qb, tid);
    copy_tile_async(s3, g_kT_lo + qb, tid);
    copy_tile_async(s4, g_s_hi  + qb, tid);
    copy_tile_async(s5, g_s_lo  + qb, tid);
    cp_commit();
    cp_wait0();
    __syncthreads();

    // phase A: O = Qr @ S
    float oacc[16][4] = {};
    gemm3(s0, s1, s4, s5, oacc, m0, n0, lane);
    __syncthreads();   // all warps done reading S slots

    // prefetch V into S slots; overlaps phase B
    copy_tile_async(s4, g_v_hi + qb, tid);
    copy_tile_async(s5, g_v_lo + qb, tid);
    cp_commit();

    // phase B: E = Qr @ Kr^T
    float eacc[16][4] = {};
    gemm3(s0, s1, s2, s3, eacc, m0, n0, lane);
    __syncthreads();   // all warps done reading KT slots

    // mask (causal within chunk) + split E -> KT slots (bf16 hi/lo)
    {
        char* eh = (char*)sm + 2 * TILE_BYTES - 0;            // s2 region
        char* el = (char*)sm + 3 * TILE_BYTES;                // s3 region
        int r = m0 + (lane >> 2), cb = n0 + (lane & 3) * 2;
        #pragma unroll
        for (int rg = 0; rg < 2; ++rg)
            #pragma unroll
            for (int nt = 0; nt < 4; ++nt)
                #pragma unroll
                for (int h = 0; h < 2; ++h) {
                    float* a = eacc[rg * 8 + nt * 2 + h];
                    int rr0 = r + rg * 16, rr1 = rr0 + 8;
                    int c = cb + nt * 16 + h * 8;
                    float v0 = (c     <= rr0) ? a[0] : 0.f;
                    float v1 = (c + 1 <= rr0) ? a[1] : 0.f;
                    float v2 = (c     <= rr1) ? a[2] : 0.f;
                    float v3 = (c + 1 <= rr1) ? a[3] : 0.f;
                    __nv_bfloat16 h0 = __float2bfloat16(v0);
                    __nv_bfloat16 h1 = __float2bfloat16(v1);
                    __nv_bfloat16 h2 = __float2bfloat16(v2);
                    __nv_bfloat16 h3 = __float2bfloat16(v3);
                    *(u32*)(eh + (rr0 * TPAD + c) * 2) = packbf(h0, h1);
                    *(u32*)(eh + (rr1 * TPAD + c) * 2) = packbf(h2, h3);
                    *(u32*)(el + (rr0 * TPAD + c) * 2) =
                        packbf(__float2bfloat16(v0 - __bfloat162float(h0)),
                               __float2bfloat16(v1 - __bfloat162float(h1)));
                    *(u32*)(el + (rr1 * TPAD + c) * 2) =
                        packbf(__float2bfloat16(v2 - __bfloat162float(h2)),
                               __float2bfloat16(v3 - __bfloat162float(h3)));
                }
    }
    cp_wait0();        // V arrived (per-thread), then barrier for E + V visibility
    __syncthreads();

    // phase C: O += E @ V
    gemm3(s2, s3, s4, s5, oacc, m0, n0, lane);

    epilogue(out + qb, oacc, m0, n0, lane);
}

// ---------------------------------------------------------------------------
extern "C" void kernel_launch(void* const* d_in, const int* in_sizes, int n_in,
                              void* d_out, int out_size) {
    (void)in_sizes; (void)n_in; (void)out_size;
    const float* Q = (const float*)d_in[0];
    const float* K = (const float*)d_in[1];
    const float* V = (const float*)d_in[2];
    float* out = (float*)d_out;

    cudaFuncSetAttribute(k_rope, cudaFuncAttributeMaxDynamicSharedMemorySize, 66048);
    cudaFuncSetAttribute(k_h,    cudaFuncAttributeMaxDynamicSharedMemorySize, 4 * TILE_BYTES);
    cudaFuncSetAttribute(k_out,  cudaFuncAttributeMaxDynamicSharedMemorySize, 6 * TILE_BYTES);

    k_tab <<<SL, HD>>>();
    k_rope<<<NT, 256, 66048>>>(Q, K, V);
    k_h   <<<NT, 256, 4 * TILE_BYTES>>>();
    k_scan<<<dim3(NB, HD), 128>>>();
    k_out <<<NT, 256, 6 * TILE_BYTES>>>(out);
}

// round 7
// speedup vs baseline: 1.4468x; 1.1932x over previous
#include <cuda_runtime.h>
#include <cuda_bf16.h>
#include <math.h>

#define NB 8
#define SL 4096
#define HD 128
#define CCH 128
#define NCH (SL / CCH)   // 32
#define NT  (NB * NCH)   // 256 tiles

#define TPAD 136                     // padded bf16 row stride in smem tiles
#define TILE_BYTES (128 * TPAD * 2)  // 34816

typedef unsigned int u32;

// ---------------------------------------------------------------------------
// Scratch (no allocations allowed)
// ---------------------------------------------------------------------------
__device__ float g_cos[SL * HD];
__device__ float g_sin[SL * HD];
__device__ float g_h  [NT * HD * HD];           // per-chunk H[d][e] fp32
__device__ __nv_bfloat16 g_q_hi [NT * 16384];   // Qr  [t][d]
__device__ __nv_bfloat16 g_q_lo [NT * 16384];
__device__ __nv_bfloat16 g_kT_hi[NT * 16384];   // Kr^T [d][t]
__device__ __nv_bfloat16 g_kT_lo[NT * 16384];
__device__ __nv_bfloat16 g_v_hi [NT * 16384];   // V   [t][e]
__device__ __nv_bfloat16 g_v_lo [NT * 16384];
__device__ __nv_bfloat16 g_s_hi [NT * 16384];   // S excl prefix [d][e]
__device__ __nv_bfloat16 g_s_lo [NT * 16384];

// ---------------------------------------------------------------------------
// Primitives (baseline PTX, valid on plain sm_100)
// ---------------------------------------------------------------------------
__device__ __forceinline__ u32 smem_u32(const void* p) {
    u32 a;
    asm("{ .reg .u64 t; cvta.to.shared.u64 t, %1; cvt.u32.u64 %0, t; }"
        : "=r"(a) : "l"(p));
    return a;
}
__device__ __forceinline__ void ldsm4(u32& r0, u32& r1, u32& r2, u32& r3, u32 a) {
    asm volatile("ldmatrix.sync.aligned.m8n8.x4.shared.b16 {%0,%1,%2,%3}, [%4];"
                 : "=r"(r0), "=r"(r1), "=r"(r2), "=r"(r3) : "r"(a));
}
__device__ __forceinline__ void ldsm4t(u32& r0, u32& r1, u32& r2, u32& r3, u32 a) {
    asm volatile("ldmatrix.sync.aligned.m8n8.x4.trans.shared.b16 {%0,%1,%2,%3}, [%4];"
                 : "=r"(r0), "=r"(r1), "=r"(r2), "=r"(r3) : "r"(a));
}
__device__ __forceinline__ void mma_bf16(float* c, u32 a0, u32 a1, u32 a2, u32 a3,
                                         u32 b0, u32 b1) {
    asm volatile(
        "mma.sync.aligned.m16n8k16.row.col.f32.bf16.bf16.f32 "
        "{%0,%1,%2,%3},{%4,%5,%6,%7},{%8,%9},{%0,%1,%2,%3};"
        : "+f"(c[0]), "+f"(c[1]), "+f"(c[2]), "+f"(c[3])
        : "r"(a0), "r"(a1), "r"(a2), "r"(a3), "r"(b0), "r"(b1));
}
__device__ __forceinline__ void cp16(u32 dst, const void* src) {
    asm volatile("cp.async.cg.shared.global [%0], [%1], 16;"
                 :: "r"(dst), "l"(src) : "memory");
}
__device__ __forceinline__ void cp_commit() {
    asm volatile("cp.async.commit_group;" ::: "memory");
}
__device__ __forceinline__ void cp_wait0() {
    asm volatile("cp.async.wait_group 0;" ::: "memory");
}
__device__ __forceinline__ void cp_wait1() {
    asm volatile("cp.async.wait_group 1;" ::: "memory");
}
__device__ __forceinline__ u32 packbf(__nv_bfloat16 lo, __nv_bfloat16 hi) {
    return (u32)__bfloat16_as_ushort(hi) << 16 | (u32)__bfloat16_as_ushort(lo);
}
__device__ __forceinline__ void split_store(__nv_bfloat16* hi, __nv_bfloat16* lo,
                                            int off, float v) {
    __nv_bfloat16 h = __float2bfloat16(v);
    hi[off] = h;
    lo[off] = __float2bfloat16(v - __bfloat162float(h));
}
// split 8 floats -> hi/lo bf16, one uint4 store each
__device__ __forceinline__ void split8_store(__nv_bfloat16* ghi, __nv_bfloat16* glo,
                                             int off, const float* v) {
    u32 hw[4], lw[4];
    #pragma unroll
    for (int j = 0; j < 4; ++j) {
        float f0 = v[2 * j], f1 = v[2 * j + 1];
        __nv_bfloat16 h0 = __float2bfloat16(f0), h1 = __float2bfloat16(f1);
        hw[j] = packbf(h0, h1);
        lw[j] = packbf(__float2bfloat16(f0 - __bfloat162float(h0)),
                       __float2bfloat16(f1 - __bfloat162float(h1)));
    }
    *(uint4*)(ghi + off) = *(uint4*)hw;
    *(uint4*)(glo + off) = *(uint4*)lw;
}
__device__ __forceinline__ void ld8(float* r, const float* p) {
    *(float4*)r       = *(const float4*)p;
    *(float4*)(r + 4) = *(const float4*)(p + 4);
}

// gmem [128][128] bf16 tile -> padded smem tile, via cp.async
__device__ __forceinline__ void copy_tile_async(u32 dst, const __nv_bfloat16* src,
                                                int tid) {
    #pragma unroll
    for (int i = 0; i < 8; ++i) {
        int j = tid + i * 256;
        int row = j >> 4, col = j & 15;
        cp16(dst + row * (TPAD * 2) + col * 16, (const char*)src + j * 16);
    }
}

// ---------------------------------------------------------------------------
// 3-term split GEMM with paired row groups + causal K-limits.
// Warp handles row groups rA (acc[0..7]) and rB (acc[8..15]), cols n0..n0+63.
// Group A is active for kk <= kkA, group B for kk <= kkB (kkA <= kkB).
// Full GEMM: kkA = kkB = 7.
// ---------------------------------------------------------------------------
__device__ __forceinline__ void gemm3(u32 ah, u32 al, u32 bh, u32 bl,
                                      float acc[16][4], int rA, int rB, int n0,
                                      int kkA, int kkB, int lane) {
    int l15 = lane & 15, lhi = (lane >> 4) << 3;
    #pragma unroll 1
    for (int kk = 0; kk <= kkB; ++kk) {
        u32 arA = (u32)(((rA + l15) * TPAD + kk * 16 + lhi) * 2);
        u32 arB = (u32)(((rB + l15) * TPAD + kk * 16 + lhi) * 2);
        u32 H1[4], L1[4];
        ldsm4(H1[0], H1[1], H1[2], H1[3], ah + arB);
        ldsm4(L1[0], L1[1], L1[2], L1[3], al + arB);
        bool doA = (kk <= kkA);
        u32 H0[4], L0[4];
        if (doA) {
            ldsm4(H0[0], H0[1], H0[2], H0[3], ah + arA);
            ldsm4(L0[0], L0[1], L0[2], L0[3], al + arA);
        }
        #pragma unroll
        for (int nt = 0; nt < 4; ++nt) {
            u32 boff = (u32)(((kk * 16 + l15) * TPAD + n0 + nt * 16 + lhi) * 2);
            u32 B0, B1, B2, B3, C0, C1, C2, C3;
            ldsm4t(B0, B1, B2, B3, bh + boff);
            ldsm4t(C0, C1, C2, C3, bl + boff);
            float* a10 = acc[8 + nt * 2];
            float* a11 = acc[8 + nt * 2 + 1];
            mma_bf16(a10, H1[0], H1[1], H1[2], H1[3], B0, B1);
            mma_bf16(a11, H1[0], H1[1], H1[2], H1[3], B2, B3);
            mma_bf16(a10, H1[0], H1[1], H1[2], H1[3], C0, C1);
            mma_bf16(a11, H1[0], H1[1], H1[2], H1[3], C2, C3);
            mma_bf16(a10, L1[0], L1[1], L1[2], L1[3], B0, B1);
            mma_bf16(a11, L1[0], L1[1], L1[2], L1[3], B2, B3);
            if (doA) {
                float* a00 = acc[nt * 2];
                float* a01 = acc[nt * 2 + 1];
                mma_bf16(a00, H0[0], H0[1], H0[2], H0[3], B0, B1);
                mma_bf16(a01, H0[0], H0[1], H0[2], H0[3], B2, B3);
                mma_bf16(a00, H0[0], H0[1], H0[2], H0[3], C0, C1);
                mma_bf16(a01, H0[0], H0[1], H0[2], H0[3], C2, C3);
                mma_bf16(a00, L0[0], L0[1], L0[2], L0[3], B0, B1);
                mma_bf16(a01, L0[0], L0[1], L0[2], L0[3], B2, B3);
            }
        }
    }
}

// acc -> gmem fp32 [128][128] tile (row groups rA / rB, cols n0..n0+63)
__device__ __forceinline__ void epilogue(float* dst, float acc[16][4],
                                         int rA, int rB, int n0, int lane) {
    int rr = lane >> 2, cb = n0 + (lane & 3) * 2;
    #pragma unroll
    for (int rg = 0; rg < 2; ++rg) {
        int base = rg ? rB : rA;
        #pragma unroll
        for (int nt = 0; nt < 4; ++nt)
            #pragma unroll
            for (int h = 0; h < 2; ++h) {
                float* a = acc[rg * 8 + nt * 2 + h];
                int r0 = base + rr, c = cb + nt * 16 + h * 8;
                *(float2*)(dst + r0 * 128 + c)       = make_float2(a[0], a[1]);
                *(float2*)(dst + (r0 + 8) * 128 + c) = make_float2(a[2], a[3]);
            }
    }
}

// ---------------------------------------------------------------------------
// Kernel 0: RoPE cos/sin table (double internally)
// ---------------------------------------------------------------------------
__global__ void k_tab() {
    int s = blockIdx.x;
    int j = threadIdx.x;
    int j2 = j & 63;
    double inv = exp(-(double)j2 * (log(10000.0) / 64.0));
    double a = (double)s * inv;
    double sv, cv;
    sincos(a, &sv, &cv);
    g_cos[s * HD + j] = (float)cv;
    g_sin[s * HD + j] = (float)sv;
}

// ---------------------------------------------------------------------------
// Kernel 1: RoPE + split-bf16 (fully vectorized: float4 loads, uint4 stores).
// Q -> g_q [t][d]; K -> g_kT [d][t]; V -> g_v [t][e].
// ---------------------------------------------------------------------------
__global__ void __launch_bounds__(256) k_rope(const float* __restrict__ Q,
                                              const float* __restrict__ K,
                                              const float* __restrict__ V) {
    extern __shared__ float buf[];   // [128][129]
    int b  = blockIdx.x >> 5;
    int ch = blockIdx.x & 31;
    int tid = threadIdx.x;
    int base  = (b * SL + ch * CCH) * HD;
    int tbase = blockIdx.x * 16384;

    #pragma unroll
    for (int i = 0; i < 8; ++i) {
        int u = tid + i * 256;          // 0..2047
        int t = u >> 4;                 // row 0..127
        int d0 = (u & 15) << 3;         // col octet base
        int s = ch * CCH + t;
        int dp = d0 ^ 64;
        float sign = (d0 < 64) ? -1.f : 1.f;

        float cs[8], sn[8], q[8], qp[8], kx[8], kp[8], vv[8];
        ld8(cs, g_cos + s * HD + d0);
        ld8(sn, g_sin + s * HD + d0);
        ld8(q,  Q + base + t * HD + d0);
        ld8(qp, Q + base + t * HD + dp);
        ld8(kx, K + base + t * HD + d0);
        ld8(kp, K + base + t * HD + dp);
        ld8(vv, V + base + t * HD + d0);

        float qo[8], ko[8];
        #pragma unroll
        for (int j = 0; j < 8; ++j) {
            qo[j] = q[j]  * cs[j] + sign * qp[j] * sn[j];
            ko[j] = kx[j] * cs[j] + sign * kp[j] * sn[j];
        }
        split8_store(g_q_hi, g_q_lo, tbase + t * HD + d0, qo);
        split8_store(g_v_hi, g_v_lo, tbase + t * HD + d0, vv);
        #pragma unroll
        for (int j = 0; j < 8; ++j) buf[t * 129 + d0 + j] = ko[j];
    }
    __syncthreads();

    // transposed K: thread reads 8 t-values at fixed d, writes uint4
    #pragma unroll
    for (int i = 0; i < 8; ++i) {
        int u = tid + i * 256;
        int d = u >> 4;
        int t0 = (u & 15) << 3;
        float kv[8];
        #pragma unroll
        for (int j = 0; j < 8; ++j) kv[j] = buf[(t0 + j) * 129 + d];
        split8_store(g_kT_hi, g_kT_lo, tbase + d * HD + t0, kv);
    }
}

// ---------------------------------------------------------------------------
// Kernel 2: per-chunk H[d][e] = sum_t Kr^T[d][t] * V[t][e]  (HMMA, 3-term)
// ---------------------------------------------------------------------------
__global__ void __launch_bounds__(256) k_h() {
    extern __shared__ char sm[];
    u32 sb = smem_u32(sm);
    int tile = blockIdx.x;
    int tid = threadIdx.x, lane = tid & 31, wid = tid >> 5;
    int rA = (wid >> 1) * 32, rB = rA + 16, n0 = (wid & 1) * 64;
    int tbase = tile * 16384;

    copy_tile_async(sb,                  g_kT_hi + tbase, tid);
    copy_tile_async(sb + TILE_BYTES,     g_kT_lo + tbase, tid);
    copy_tile_async(sb + 2 * TILE_BYTES, g_v_hi  + tbase, tid);
    copy_tile_async(sb + 3 * TILE_BYTES, g_v_lo  + tbase, tid);
    cp_commit();
    cp_wait0();
    __syncthreads();

    float acc[16][4] = {};
    gemm3(sb, sb + TILE_BYTES, sb + 2 * TILE_BYTES, sb + 3 * TILE_BYTES,
          acc, rA, rB, n0, 7, 7, lane);
    epilogue(g_h + tbase, acc, rA, rB, n0, lane);
}

// ---------------------------------------------------------------------------
// Kernel 3: exclusive prefix scan of H over chunks -> split-bf16 S tiles.
// ---------------------------------------------------------------------------
__global__ void __launch_bounds__(128) k_scan() {
    int b = blockIdx.x, d = blockIdx.y, e = threadIdx.x;
    float vals[NCH];
    #pragma unroll
    for (int i = 0; i < NCH; ++i)
        vals[i] = g_h[(b * NCH + i) * 16384 + d * 128 + e];
    int o = d * 128 + e;
    float run = 0.f;
    #pragma unroll
    for (int i = 0; i < NCH; ++i) {
        int tb = (b * NCH + i) * 16384;
        split_store(g_s_hi, g_s_lo, tb + o, run);
        run += vals[i];
    }
}

// ---------------------------------------------------------------------------
// Kernel 4: out = tril(Qr Kr^T) V + Qr S  per (b, chunk).
// Paired row groups: warp mr handles rows {16*mr, 16*(7-mr)} (balanced causal).
// Slots: s0/s1 = Q, s2/s3 = KT -> E, s4/s5 = S -> V.
// Load pipeline: g1 = Q+S (phase A), g2 = KT (streams under A), g3 = V
// (streams under B). Phase C uses causal K-limits (kkA=mr, kkB=7-mr).
// ---------------------------------------------------------------------------
__global__ void __launch_bounds__(256) k_out(float* __restrict__ out) {
    extern __shared__ char sm[];
    u32 sb = smem_u32(sm);
    int tile = blockIdx.x;
    int tid = threadIdx.x, lane = tid & 31, wid = tid >> 5;
    int qb = tile * 16384;
    int mr = wid >> 1, nc = wid & 1;
    int rA = 16 * mr, rB = 16 * (7 - mr), n0 = nc * 64;

    u32 s0 = sb, s1 = sb + TILE_BYTES, s2 = sb + 2 * TILE_BYTES,
        s3 = sb + 3 * TILE_BYTES, s4 = sb + 4 * TILE_BYTES, s5 = sb + 5 * TILE_BYTES;

    // g1: Q + S (needed first, for phase A)
    copy_tile_async(s0, g_q_hi + qb, tid);
    copy_tile_async(s1, g_q_lo + qb, tid);
    copy_tile_async(s4, g_s_hi + qb, tid);
    copy_tile_async(s5, g_s_lo + qb, tid);
    cp_commit();
    // g2: KT (streams under phase A)
    copy_tile_async(s2, g_kT_hi + qb, tid);
    copy_tile_async(s3, g_kT_lo + qb, tid);
    cp_commit();

    cp_wait1();        // g1 done (g2 may still be in flight)
    __syncthreads();

    // phase A: O = Qr @ S
    float oacc[16][4] = {};
    gemm3(s0, s1, s4, s5, oacc, rA, rB, n0, 7, 7, lane);

    cp_wait0();        // g2 (KT) done
    __syncthreads();   // all warps done reading S; KT visible

    // g3: V into S slots (streams under phase B)
    copy_tile_async(s4, g_v_hi + qb, tid);
    copy_tile_async(s5, g_v_lo + qb, tid);
    cp_commit();

    // phase B: E = Qr @ Kr^T
    float eacc[16][4] = {};
    gemm3(s0, s1, s2, s3, eacc, rA, rB, n0, 7, 7, lane);
    __syncthreads();   // all warps done reading KT slots

    // mask (causal within chunk) + split E -> KT slots (bf16 hi/lo)
    {
        char* eh = (char*)sm + 2 * TILE_BYTES;
        char* el = (char*)sm + 3 * TILE_BYTES;
        int rr = lane >> 2, cb = n0 + (lane & 3) * 2;
        #pragma unroll
        for (int rg = 0; rg < 2; ++rg) {
            int base = rg ? rB : rA;
            #pragma unroll
            for (int nt = 0; nt < 4; ++nt)
                #pragma unroll
                for (int h = 0; h < 2; ++h) {
                    float* a = eacc[rg * 8 + nt * 2 + h];
                    int rr0 = base + rr, rr1 = rr0 + 8;
                    int c = cb + nt * 16 + h * 8;
                    float v0 = (c     <= rr0) ? a[0] : 0.f;
                    float v1 = (c + 1 <= rr0) ? a[1] : 0.f;
                    float v2 = (c     <= rr1) ? a[2] : 0.f;
                    float v3 = (c + 1 <= rr1) ? a[3] : 0.f;
                    __nv_bfloat16 h0 = __float2bfloat16(v0);
                    __nv_bfloat16 h1 = __float2bfloat16(v1);
                    __nv_bfloat16 h2 = __float2bfloat16(v2);
                    __nv_bfloat16 h3 = __float2bfloat16(v3);
                    *(u32*)(eh + (rr0 * TPAD + c) * 2) = packbf(h0, h1);
                    *(u32*)(eh + (rr1 * TPAD + c) * 2) = packbf(h2, h3);
                    *(u32*)(el + (rr0 * TPAD + c) * 2) =
                        packbf(__float2bfloat16(v0 - __bfloat162float(h0)),
                               __float2bfloat16(v1 - __bfloat162float(h1)));
                    *(u32*)(el + (rr1 * TPAD + c) * 2) =
                        packbf(__float2bfloat16(v2 - __bfloat162float(h2)),
                               __float2bfloat16(v3 - __bfloat162float(h3)));
                }
        }
    }
    cp_wait0();        // V arrived
    __syncthreads();   // E + V visible to all warps

    // phase C: O += E @ V  (causal: group A kk<=mr, group B kk<=7-mr)
    gemm3(s2, s3, s4, s5, oacc, rA, rB, n0, mr, 7 - mr, lane);

    epilogue(out + qb, oacc, rA, rB, n0, lane);
}

// ---------------------------------------------------------------------------
extern "C" void kernel_launch(void* const* d_in, const int* in_sizes, int n_in,
                              void* d_out, int out_size) {
    (void)in_sizes; (void)n_in; (void)out_size;
    const float* Q = (const float*)d_in[0];
    const float* K = (const float*)d_in[1];
    const float* V = (const float*)d_in[2];
    float* out = (float*)d_out;

    cudaFuncSetAttribute(k_rope, cudaFuncAttributeMaxDynamicSharedMemorySize, 66048);
    cudaFuncSetAttribute(k_h,    cudaFuncAttributeMaxDynamicSharedMemorySize, 4 * TILE_BYTES);
    cudaFuncSetAttribute(k_out,  cudaFuncAttributeMaxDynamicSharedMemorySize, 6 * TILE_BYTES);

    k_tab <<<SL, HD>>>();
    k_rope<<<NT, 256, 66048>>>(Q, K, V);
    k_h   <<<NT, 256, 4 * TILE_BYTES>>>();
    k_scan<<<dim3(NB, HD), 128>>>();
    k_out <<<NT, 256, 6 * TILE_BYTES>>>(out);
}

// round 8
// speedup vs baseline: 1.4783x; 1.0217x over previous
#include <cuda_runtime.h>
#include <cuda_bf16.h>
#include <math.h>

#define NB 8
#define SL 4096
#define HD 128
#define CCH 128
#define NCH (SL / CCH)   // 32
#define NT  (NB * NCH)   // 256 tiles

#define TPAD 136                     // padded bf16 row stride in smem tiles
#define TILE_BYTES (128 * TPAD * 2)  // 34816

typedef unsigned int u32;

// ---------------------------------------------------------------------------
// Scratch (no allocations allowed)
// ---------------------------------------------------------------------------
__device__ float g_cos[SL * HD];
__device__ float g_sin[SL * HD];
__device__ float g_h  [NT * HD * HD];           // per-chunk H[d][e] fp32
__device__ __nv_bfloat16 g_q_hi [NT * 16384];   // Qr  [t][d]
__device__ __nv_bfloat16 g_q_lo [NT * 16384];
__device__ __nv_bfloat16 g_kT_hi[NT * 16384];   // Kr^T [d][t]
__device__ __nv_bfloat16 g_kT_lo[NT * 16384];
__device__ __nv_bfloat16 g_v_hi [NT * 16384];   // V   [t][e]
__device__ __nv_bfloat16 g_v_lo [NT * 16384];
__device__ __nv_bfloat16 g_s_hi [NT * 16384];   // S excl prefix [d][e]
__device__ __nv_bfloat16 g_s_lo [NT * 16384];

// ---------------------------------------------------------------------------
// Primitives (baseline PTX, valid on plain sm_100)
// ---------------------------------------------------------------------------
__device__ __forceinline__ u32 smem_u32(const void* p) {
    u32 a;
    asm("{ .reg .u64 t; cvta.to.shared.u64 t, %1; cvt.u32.u64 %0, t; }"
        : "=r"(a) : "l"(p));
    return a;
}
__device__ __forceinline__ void ldsm4(u32& r0, u32& r1, u32& r2, u32& r3, u32 a) {
    asm volatile("ldmatrix.sync.aligned.m8n8.x4.shared.b16 {%0,%1,%2,%3}, [%4];"
                 : "=r"(r0), "=r"(r1), "=r"(r2), "=r"(r3) : "r"(a));
}
__device__ __forceinline__ void ldsm4t(u32& r0, u32& r1, u32& r2, u32& r3, u32 a) {
    asm volatile("ldmatrix.sync.aligned.m8n8.x4.trans.shared.b16 {%0,%1,%2,%3}, [%4];"
                 : "=r"(r0), "=r"(r1), "=r"(r2), "=r"(r3) : "r"(a));
}
__device__ __forceinline__ void mma_bf16(float* c, u32 a0, u32 a1, u32 a2, u32 a3,
                                         u32 b0, u32 b1) {
    asm volatile(
        "mma.sync.aligned.m16n8k16.row.col.f32.bf16.bf16.f32 "
        "{%0,%1,%2,%3},{%4,%5,%6,%7},{%8,%9},{%0,%1,%2,%3};"
        : "+f"(c[0]), "+f"(c[1]), "+f"(c[2]), "+f"(c[3])
        : "r"(a0), "r"(a1), "r"(a2), "r"(a3), "r"(b0), "r"(b1));
}
__device__ __forceinline__ void cp16(u32 dst, const void* src) {
    asm volatile("cp.async.cg.shared.global [%0], [%1], 16;"
                 :: "r"(dst), "l"(src) : "memory");
}
__device__ __forceinline__ void cp_commit() {
    asm volatile("cp.async.commit_group;" ::: "memory");
}
__device__ __forceinline__ void cp_wait0() {
    asm volatile("cp.async.wait_group 0;" ::: "memory");
}
__device__ __forceinline__ void cp_wait1() {
    asm volatile("cp.async.wait_group 1;" ::: "memory");
}
__device__ __forceinline__ u32 packbf(__nv_bfloat16 lo, __nv_bfloat16 hi) {
    return (u32)__bfloat16_as_ushort(hi) << 16 | (u32)__bfloat16_as_ushort(lo);
}
__device__ __forceinline__ void split_store(__nv_bfloat16* hi, __nv_bfloat16* lo,
                                            int off, float v) {
    __nv_bfloat16 h = __float2bfloat16(v);
    hi[off] = h;
    lo[off] = __float2bfloat16(v - __bfloat162float(h));
}
// split 8 floats -> hi/lo bf16, one uint4 store each
__device__ __forceinline__ void split8_store(__nv_bfloat16* ghi, __nv_bfloat16* glo,
                                             int off, const float* v) {
    u32 hw[4], lw[4];
    #pragma unroll
    for (int j = 0; j < 4; ++j) {
        float f0 = v[2 * j], f1 = v[2 * j + 1];
        __nv_bfloat16 h0 = __float2bfloat16(f0), h1 = __float2bfloat16(f1);
        hw[j] = packbf(h0, h1);
        lw[j] = packbf(__float2bfloat16(f0 - __bfloat162float(h0)),
                       __float2bfloat16(f1 - __bfloat162float(h1)));
    }
    *(uint4*)(ghi + off) = *(uint4*)hw;
    *(uint4*)(glo + off) = *(uint4*)lw;
}
__device__ __forceinline__ void ld8(float* r, const float* p) {
    *(float4*)r       = *(const float4*)p;
    *(float4*)(r + 4) = *(const float4*)(p + 4);
}

// gmem [128][128] bf16 tile -> padded smem tile, via cp.async (NTHR threads)
template<int NTHR>
__device__ __forceinline__ void copy_tile_async(u32 dst, const __nv_bfloat16* src,
                                                int tid) {
    #pragma unroll
    for (int i = 0; i < 2048 / NTHR; ++i) {
        int j = tid + i * NTHR;
        int row = j >> 4, col = j & 15;
        cp16(dst + row * (TPAD * 2) + col * 16, (const char*)src + j * 16);
    }
}

// ---------------------------------------------------------------------------
// 3-term split GEMM, warp tile 16x64, K=128 (kk <= kkmax).
// A row group r0 (16 rows), cols n0..n0+63. acc[8][4], frag idx = nt*2 + h.
// ---------------------------------------------------------------------------
__device__ __forceinline__ void gemm3(u32 ah, u32 al, u32 bh, u32 bl,
                                      float acc[8][4], int r0, int n0,
                                      int kkmax, int lane) {
    int l15 = lane & 15, lhi = (lane >> 4) << 3;
    #pragma unroll 1
    for (int kk = 0; kk <= kkmax; ++kk) {
        u32 ar = (u32)(((r0 + l15) * TPAD + kk * 16 + lhi) * 2);
        u32 H[4], L[4];
        ldsm4(H[0], H[1], H[2], H[3], ah + ar);
        ldsm4(L[0], L[1], L[2], L[3], al + ar);
        #pragma unroll
        for (int nt = 0; nt < 4; ++nt) {
            u32 boff = (u32)(((kk * 16 + l15) * TPAD + n0 + nt * 16 + lhi) * 2);
            u32 B0, B1, B2, B3, C0, C1, C2, C3;
            ldsm4t(B0, B1, B2, B3, bh + boff);
            ldsm4t(C0, C1, C2, C3, bl + boff);
            float* a0 = acc[nt * 2];
            float* a1 = acc[nt * 2 + 1];
            mma_bf16(a0, H[0], H[1], H[2], H[3], B0, B1);
            mma_bf16(a1, H[0], H[1], H[2], H[3], B2, B3);
            mma_bf16(a0, H[0], H[1], H[2], H[3], C0, C1);
            mma_bf16(a1, H[0], H[1], H[2], H[3], C2, C3);
            mma_bf16(a0, L[0], L[1], L[2], L[3], B0, B1);
            mma_bf16(a1, L[0], L[1], L[2], L[3], B2, B3);
        }
    }
}

// acc -> gmem fp32 [128][128] tile (row group r0, cols n0..n0+63)
__device__ __forceinline__ void epilogue(float* dst, float acc[8][4],
                                         int r0, int n0, int lane) {
    int rr = r0 + (lane >> 2), cb = n0 + (lane & 3) * 2;
    #pragma unroll
    for (int nt = 0; nt < 4; ++nt)
        #pragma unroll
        for (int h = 0; h < 2; ++h) {
            float* a = acc[nt * 2 + h];
            int c = cb + nt * 16 + h * 8;
            *(float2*)(dst + rr * 128 + c)       = make_float2(a[0], a[1]);
            *(float2*)(dst + (rr + 8) * 128 + c) = make_float2(a[2], a[3]);
        }
}

// ---------------------------------------------------------------------------
// Kernel 0: RoPE cos/sin table (double internally)
// ---------------------------------------------------------------------------
__global__ void k_tab() {
    int s = blockIdx.x;
    int j = threadIdx.x;
    int j2 = j & 63;
    double inv = exp(-(double)j2 * (log(10000.0) / 64.0));
    double a = (double)s * inv;
    double sv, cv;
    sincos(a, &sv, &cv);
    g_cos[s * HD + j] = (float)cv;
    g_sin[s * HD + j] = (float)sv;
}

// ---------------------------------------------------------------------------
// Kernel 1: RoPE + split-bf16 (vectorized). Q -> g_q; K -> g_kT; V -> g_v.
// ---------------------------------------------------------------------------
__global__ void __launch_bounds__(256) k_rope(const float* __restrict__ Q,
                                              const float* __restrict__ K,
                                              const float* __restrict__ V) {
    extern __shared__ float buf[];   // [128][129]
    int b  = blockIdx.x >> 5;
    int ch = blockIdx.x & 31;
    int tid = threadIdx.x;
    int base  = (b * SL + ch * CCH) * HD;
    int tbase = blockIdx.x * 16384;

    #pragma unroll
    for (int i = 0; i < 8; ++i) {
        int u = tid + i * 256;
        int t = u >> 4;
        int d0 = (u & 15) << 3;
        int s = ch * CCH + t;
        int dp = d0 ^ 64;
        float sign = (d0 < 64) ? -1.f : 1.f;

        float cs[8], sn[8], q[8], qp[8], kx[8], kp[8], vv[8];
        ld8(cs, g_cos + s * HD + d0);
        ld8(sn, g_sin + s * HD + d0);
        ld8(q,  Q + base + t * HD + d0);
        ld8(qp, Q + base + t * HD + dp);
        ld8(kx, K + base + t * HD + d0);
        ld8(kp, K + base + t * HD + dp);
        ld8(vv, V + base + t * HD + d0);

        float qo[8], ko[8];
        #pragma unroll
        for (int j = 0; j < 8; ++j) {
            qo[j] = q[j]  * cs[j] + sign * qp[j] * sn[j];
            ko[j] = kx[j] * cs[j] + sign * kp[j] * sn[j];
        }
        split8_store(g_q_hi, g_q_lo, tbase + t * HD + d0, qo);
        split8_store(g_v_hi, g_v_lo, tbase + t * HD + d0, vv);
        #pragma unroll
        for (int j = 0; j < 8; ++j) buf[t * 129 + d0 + j] = ko[j];
    }
    __syncthreads();

    #pragma unroll
    for (int i = 0; i < 8; ++i) {
        int u = tid + i * 256;
        int d = u >> 4;
        int t0 = (u & 15) << 3;
        float kv[8];
        #pragma unroll
        for (int j = 0; j < 8; ++j) kv[j] = buf[(t0 + j) * 129 + d];
        split8_store(g_kT_hi, g_kT_lo, tbase + d * HD + t0, kv);
    }
}

// ---------------------------------------------------------------------------
// Kernel 2: per-chunk H[d][e] = sum_t Kr^T[d][t] * V[t][e].
// 512 threads, 16 warps, warp tile 16x64.
// ---------------------------------------------------------------------------
__global__ void __launch_bounds__(512) k_h() {
    extern __shared__ char sm[];
    u32 sb = smem_u32(sm);
    int tile = blockIdx.x;
    int tid = threadIdx.x, lane = tid & 31, wid = tid >> 5;
    int r0 = (wid >> 1) * 16, n0 = (wid & 1) * 64;
    int tbase = tile * 16384;

    copy_tile_async<512>(sb,                  g_kT_hi + tbase, tid);
    copy_tile_async<512>(sb + TILE_BYTES,     g_kT_lo + tbase, tid);
    copy_tile_async<512>(sb + 2 * TILE_BYTES, g_v_hi  + tbase, tid);
    copy_tile_async<512>(sb + 3 * TILE_BYTES, g_v_lo  + tbase, tid);
    cp_commit();
    cp_wait0();
    __syncthreads();

    float acc[8][4] = {};
    gemm3(sb, sb + TILE_BYTES, sb + 2 * TILE_BYTES, sb + 3 * TILE_BYTES,
          acc, r0, n0, 7, lane);
    epilogue(g_h + tbase, acc, r0, n0, lane);
}

// ---------------------------------------------------------------------------
// Kernel 3: exclusive prefix scan of H over chunks -> split-bf16 S tiles.
// ---------------------------------------------------------------------------
__global__ void __launch_bounds__(128) k_scan() {
    int b = blockIdx.x, d = blockIdx.y, e = threadIdx.x;
    float vals[NCH];
    #pragma unroll
    for (int i = 0; i < NCH; ++i)
        vals[i] = g_h[(b * NCH + i) * 16384 + d * 128 + e];
    int o = d * 128 + e;
    float run = 0.f;
    #pragma unroll
    for (int i = 0; i < NCH; ++i) {
        int tb = (b * NCH + i) * 16384;
        split_store(g_s_hi, g_s_lo, tb + o, run);
        run += vals[i];
    }
}

// ---------------------------------------------------------------------------
// Kernel 4: out = tril(Qr Kr^T) V + Qr S  per (b, chunk). 512 threads.
// Warp (g = wid>>1, nc = wid&1): rows 16g..16g+15, cols 64nc..64nc+63.
// Slots: s0/s1 = Q, s2/s3 = KT -> E, s4/s5 = S -> V.
// Phase C causal: warp group g needs only kk <= g.
// ---------------------------------------------------------------------------
__global__ void __launch_bounds__(512) k_out(float* __restrict__ out) {
    extern __shared__ char sm[];
    u32 sb = smem_u32(sm);
    int tile = blockIdx.x;
    int tid = threadIdx.x, lane = tid & 31, wid = tid >> 5;
    int qb = tile * 16384;
    int g = wid >> 1, nc = wid & 1;
    int r0 = 16 * g, n0 = 64 * nc;

    u32 s0 = sb, s1 = sb + TILE_BYTES, s2 = sb + 2 * TILE_BYTES,
        s3 = sb + 3 * TILE_BYTES, s4 = sb + 4 * TILE_BYTES, s5 = sb + 5 * TILE_BYTES;

    // g1: Q + S (phase A operands)
    copy_tile_async<512>(s0, g_q_hi + qb, tid);
    copy_tile_async<512>(s1, g_q_lo + qb, tid);
    copy_tile_async<512>(s4, g_s_hi + qb, tid);
    copy_tile_async<512>(s5, g_s_lo + qb, tid);
    cp_commit();
    // g2: KT (streams under phase A)
    copy_tile_async<512>(s2, g_kT_hi + qb, tid);
    copy_tile_async<512>(s3, g_kT_lo + qb, tid);
    cp_commit();

    cp_wait1();
    __syncthreads();

    // phase A: O = Qr @ S
    float oacc[8][4] = {};
    gemm3(s0, s1, s4, s5, oacc, r0, n0, 7, lane);

    cp_wait0();        // KT arrived
    __syncthreads();   // all warps done reading S; KT visible

    // g3: V into S slots (streams under phase B)
    copy_tile_async<512>(s4, g_v_hi + qb, tid);
    copy_tile_async<512>(s5, g_v_lo + qb, tid);
    cp_commit();

    // phase B: E = Qr @ Kr^T
    float eacc[8][4] = {};
    gemm3(s0, s1, s2, s3, eacc, r0, n0, 7, lane);
    __syncthreads();   // all warps done reading KT slots

    // mask (causal within chunk) + split E -> KT slots (bf16 hi/lo)
    {
        char* eh = (char*)sm + 2 * TILE_BYTES;
        char* el = (char*)sm + 3 * TILE_BYTES;
        int rr0 = r0 + (lane >> 2), rr1 = rr0 + 8;
        int cb = n0 + (lane & 3) * 2;
        #pragma unroll
        for (int nt = 0; nt < 4; ++nt)
            #pragma unroll
            for (int h = 0; h < 2; ++h) {
                float* a = eacc[nt * 2 + h];
                int c = cb + nt * 16 + h * 8;
                float v0 = (c     <= rr0) ? a[0] : 0.f;
                float v1 = (c + 1 <= rr0) ? a[1] : 0.f;
                float v2 = (c     <= rr1) ? a[2] : 0.f;
                float v3 = (c + 1 <= rr1) ? a[3] : 0.f;
                __nv_bfloat16 h0 = __float2bfloat16(v0);
                __nv_bfloat16 h1 = __float2bfloat16(v1);
                __nv_bfloat16 h2 = __float2bfloat16(v2);
                __nv_bfloat16 h3 = __float2bfloat16(v3);
                *(u32*)(eh + (rr0 * TPAD + c) * 2) = packbf(h0, h1);
                *(u32*)(eh + (rr1 * TPAD + c) * 2) = packbf(h2, h3);
                *(u32*)(el + (rr0 * TPAD + c) * 2) =
                    packbf(__float2bfloat16(v0 - __bfloat162float(h0)),
                           __float2bfloat16(v1 - __bfloat162float(h1)));
                *(u32*)(el + (rr1 * TPAD + c) * 2) =
                    packbf(__float2bfloat16(v2 - __bfloat162float(h2)),
                           __float2bfloat16(v3 - __bfloat162float(h3)));
            }
    }
    cp_wait0();        // V arrived
    __syncthreads();   // E + V visible to all warps

    // phase C: O += E @ V  (warp group g: E rows zero beyond t = 16g+15)
    gemm3(s2, s3, s4, s5, oacc, r0, n0, g, lane);

    epilogue(out + qb, oacc, r0, n0, lane);
}

// ---------------------------------------------------------------------------
extern "C" void kernel_launch(void* const* d_in, const int* in_sizes, int n_in,
                              void* d_out, int out_size) {
    (void)in_sizes; (void)n_in; (void)out_size;
    const float* Q = (const float*)d_in[0];
    const float* K = (const float*)d_in[1];
    const float* V = (const float*)d_in[2];
    float* out = (float*)d_out;

    cudaFuncSetAttribute(k_rope, cudaFuncAttributeMaxDynamicSharedMemorySize, 66048);
    cudaFuncSetAttribute(k_h,    cudaFuncAttributeMaxDynamicSharedMemorySize, 4 * TILE_BYTES);
    cudaFuncSetAttribute(k_out,  cudaFuncAttributeMaxDynamicSharedMemorySize, 6 * TILE_BYTES);

    k_tab <<<SL, HD>>>();
    k_rope<<<NT, 256, 66048>>>(Q, K, V);
    k_h   <<<NT, 512, 4 * TILE_BYTES>>>();
    k_scan<<<dim3(NB, HD), 128>>>();
    k_out <<<NT, 512, 6 * TILE_BYTES>>>(out);
}